// round 17
// baseline (speedup 1.0000x reference)
#include <cuda_runtime.h>
#include <cuda_bf16.h>
#include <math.h>
#include <stdint.h>

#define NBATCH 16
#define LSEQ   4096
#define DIN    64
#define HCH    256
#define NST    32
#define NLAY   4
#define DOUT   10

typedef unsigned long long ull;

// ===========================================================================
// Base-ISA PTX helpers (compute_103 base — no tcgen05 / 'a'-suffix features)
// ===========================================================================
__device__ __forceinline__ uint32_t smem_u32(const void* p) {
    uint32_t a;
    asm("{ .reg .u64 t; cvta.to.shared.u64 t, %1; cvt.u32.u64 %0, t; }"
        : "=r"(a) : "l"(p));
    return a;
}
__device__ __forceinline__ void cp16(uint32_t dst, const void* src) {
    asm volatile("cp.async.cg.shared.global [%0], [%1], 16;"
                 :: "r"(dst), "l"(src));
}
#define CP_COMMIT() asm volatile("cp.async.commit_group;" ::: "memory")
#define CP_WAIT0()  asm volatile("cp.async.wait_group 0;" ::: "memory")
#define CP_WAIT1()  asm volatile("cp.async.wait_group 1;" ::: "memory")

__device__ __forceinline__ void ldsm4(uint32_t* r, uint32_t addr) {
    asm volatile("ldmatrix.sync.aligned.m8n8.x4.shared.b16 {%0,%1,%2,%3}, [%4];"
                 : "=r"(r[0]), "=r"(r[1]), "=r"(r[2]), "=r"(r[3]) : "r"(addr));
}
__device__ __forceinline__ void ldsm4t(uint32_t* r, uint32_t addr) {
    asm volatile("ldmatrix.sync.aligned.m8n8.x4.trans.shared.b16 {%0,%1,%2,%3}, [%4];"
                 : "=r"(r[0]), "=r"(r[1]), "=r"(r[2]), "=r"(r[3]) : "r"(addr));
}
__device__ __forceinline__ void mma_bf16(float* d, const uint32_t* a,
                                         uint32_t b0, uint32_t b1) {
    asm volatile(
        "mma.sync.aligned.m16n8k16.row.col.f32.bf16.bf16.f32 "
        "{%0,%1,%2,%3}, {%4,%5,%6,%7}, {%8,%9}, {%0,%1,%2,%3};"
        : "+f"(d[0]), "+f"(d[1]), "+f"(d[2]), "+f"(d[3])
        : "r"(a[0]), "r"(a[1]), "r"(a[2]), "r"(a[3]), "r"(b0), "r"(b1));
}

// ===========================================================================
// Packed fp32x2 helpers
// ===========================================================================
__device__ __forceinline__ ull pack2(float x, float y) {
    ull r;
    asm("mov.b64 %0, {%1, %2};" : "=l"(r) : "f"(x), "f"(y));
    return r;
}
__device__ __forceinline__ void fma2(ull& d, ull a, ull b) {
    asm("fma.rn.f32x2 %0, %1, %2, %0;" : "+l"(d) : "l"(a), "l"(b));
}
__device__ __forceinline__ void add2(ull& d, ull a) {
    asm("add.rn.f32x2 %0, %0, %1;" : "+l"(d) : "l"(a));
}
__device__ __forceinline__ float2 unpack2(ull v) {
    float2 r;
    asm("mov.b64 {%0, %1}, %2;" : "=f"(r.x), "=f"(r.y) : "l"(v));
    return r;
}

// ===========================================================================
// Device scratch
// ===========================================================================
__device__ float g_h[NBATCH * HCH * LSEQ];                       // (B,H,L)
__device__ __nv_bfloat16 g_yh[(size_t)NBATCH * HCH * LSEQ];      // y hi, [c][l]
__device__ __nv_bfloat16 g_yl[(size_t)NBATCH * HCH * LSEQ];      // y lo, [c][l]
__device__ __nv_bfloat16 g_wh[NLAY * 512 * HCH];                 // out_w hi
__device__ __nv_bfloat16 g_wl[NLAY * 512 * HCH];                 // out_w lo
__device__ float g_par[NLAY][4][HCH * NST];

// ===========================================================================
// Prep: SSM parameter precompute + out_w bf16 hi/lo split (merged).
// ===========================================================================
__global__ void prep_kernel(const float* __restrict__ log_dt,
                            const float* __restrict__ log_A_real,
                            const float* __restrict__ A_imag,
                            const float* __restrict__ C_re,
                            const float* __restrict__ C_im,
                            const float* __restrict__ out_w) {
    int idx = blockIdx.x * blockDim.x + threadIdx.x;
    if (idx < NLAY * 512 * HCH) {
        float w = out_w[idx];
        __nv_bfloat16 hi = __float2bfloat16(w);
        g_wh[idx] = hi;
        g_wl[idx] = __float2bfloat16(w - __bfloat162float(hi));
    }
    if (idx < NLAY * HCH * NST) {
        int layer = idx / (HCH * NST);
        int hn    = idx - layer * (HCH * NST);
        int h     = hn / NST;

        float dt  = expf(log_dt[layer * HCH + h]);
        float Are = -expf(log_A_real[idx]);
        float Aim = A_imag[idx];
        float dre = Are * dt;
        float dimg = Aim * dt;

        float sy, cy;
        sincosf(dimg, &sy, &cy);
        float em1 = expm1f(dre);
        float ex  = em1 + 1.0f;
        float wre = ex * cy;
        float wim = ex * sy;
        float emr = fmaf(em1, cy, cy - 1.0f);
        float emi = ex * sy;

        float inv = 1.0f / fmaf(Are, Are, Aim * Aim);
        float tre = fmaf(emr, Are, emi * Aim) * inv;
        float tim = fmaf(emi, Are, -emr * Aim) * inv;

        float cre = C_re[idx], cim = C_im[idx];
        float ctre = fmaf(cre, tre, -cim * tim);
        float ctim = fmaf(cre, tim, cim * tre);

        g_par[layer][0][hn] = wre;
        g_par[layer][1][hn] = wim;
        g_par[layer][2][hn] = 2.0f * ctre;
        g_par[layer][3][hn] = -2.0f * ctim;
    }
}

// ===========================================================================
// Encoder
// ===========================================================================
__global__ void __launch_bounds__(256) encoder_kernel(
    const float* __restrict__ x,
    const float* __restrict__ enc_w,
    const float* __restrict__ enc_b) {
    extern __shared__ float sm[];
    float* Wsh = sm;               // [64][256]
    float* Xsh = sm + 64 * HCH;    // [64][68]

    int b    = blockIdx.y;
    int pos0 = blockIdx.x * 64;
    int tid  = threadIdx.x;

    {
        const float4* wrow = (const float4*)(enc_w + (size_t)tid * DIN);
#pragma unroll
        for (int q = 0; q < 16; q++) {
            float4 v = wrow[q];
            Wsh[(q * 4 + 0) * HCH + tid] = v.x;
            Wsh[(q * 4 + 1) * HCH + tid] = v.y;
            Wsh[(q * 4 + 2) * HCH + tid] = v.z;
            Wsh[(q * 4 + 3) * HCH + tid] = v.w;
        }
    }
    {
#pragma unroll
        for (int k = 0; k < 4; k++) {
            int e  = tid + k * 256;
            int l  = e >> 4;
            int i4 = e & 15;
            const float4* xr =
                (const float4*)(x + ((size_t)(b * LSEQ) + pos0 + l) * DIN);
            float4 v = xr[i4];
            Xsh[(i4 * 4 + 0) * 68 + l] = v.x;
            Xsh[(i4 * 4 + 1) * 68 + l] = v.y;
            Xsh[(i4 * 4 + 2) * 68 + l] = v.z;
            Xsh[(i4 * 4 + 3) * 68 + l] = v.w;
        }
    }
    __syncthreads();

    int th = tid >> 3;
    int tl = tid & 7;
    ull acc2[8][4];
#pragma unroll
    for (int r = 0; r < 8; r++)
#pragma unroll
        for (int c = 0; c < 4; c++) acc2[r][c] = 0ULL;

    for (int i = 0; i < DIN; i++) {
        float4 a0 = *(const float4*)&Wsh[i * HCH + th * 8];
        float4 a1 = *(const float4*)&Wsh[i * HCH + th * 8 + 4];
        ulonglong2 b0 = *(const ulonglong2*)&Xsh[i * 68 + tl * 8];
        ulonglong2 b1 = *(const ulonglong2*)&Xsh[i * 68 + tl * 8 + 4];
        ull bv[4] = {b0.x, b0.y, b1.x, b1.y};
        float av[8] = {a0.x, a0.y, a0.z, a0.w, a1.x, a1.y, a1.z, a1.w};
#pragma unroll
        for (int r = 0; r < 8; r++) {
            ull ar = pack2(av[r], av[r]);
#pragma unroll
            for (int c = 0; c < 4; c++) fma2(acc2[r][c], ar, bv[c]);
        }
    }

#pragma unroll
    for (int r = 0; r < 8; r++) {
        int h = th * 8 + r;
        float bias = __ldg(&enc_b[h]);
        float* dst = g_h + ((size_t)(b * HCH + h)) * LSEQ + pos0 + tl * 8;
        float2 p0 = unpack2(acc2[r][0]);
        float2 p1 = unpack2(acc2[r][1]);
        float2 p2 = unpack2(acc2[r][2]);
        float2 p3 = unpack2(acc2[r][3]);
        float4 o0 = make_float4(p0.x + bias, p0.y + bias, p1.x + bias, p1.y + bias);
        float4 o1 = make_float4(p2.x + bias, p2.y + bias, p3.x + bias, p3.y + bias);
        ((float4*)dst)[0] = o0;
        ((float4*)dst)[1] = o1;
    }
}

// ===========================================================================
// SSM scan + D-skip + GELU -> bf16 hi/lo, [c][l] layout. (R12 body verbatim)
// ===========================================================================
__global__ void __launch_bounds__(128) scan_kernel(const float* __restrict__ Dvec,
                                                   int layer) {
    __shared__ float sh[4][32][36];
    int tid  = threadIdx.x;
    int wid  = tid >> 5;
    int lane = tid & 31;
    int c    = blockIdx.x * 4 + wid;
    int h    = c & (HCH - 1);

    const float* par = &g_par[layer][0][0];
    float wre = par[0 * (HCH * NST) + h * NST + lane];
    float wim = par[1 * (HCH * NST) + h * NST + lane];
    float ca  = par[2 * (HCH * NST) + h * NST + lane];
    float cb  = par[3 * (HCH * NST) + h * NST + lane];
    float Dh  = __ldg(&Dvec[layer * HCH + h]);

    const float* zin = g_h + (size_t)c * LSEQ;
    __nv_bfloat16* yh = g_yh + (size_t)c * LSEQ;
    __nv_bfloat16* yl = g_yl + (size_t)c * LSEQ;
    float (*S)[36] = sh[wid];

    float sre = 0.0f, sim = 0.0f;
    float zv = zin[lane];
    for (int l0 = 0; l0 < LSEQ; l0 += 32) {
        float zn = (l0 + 32 < LSEQ) ? zin[l0 + 32 + lane] : 0.0f;
#pragma unroll
        for (int t = 0; t < 32; t++) {
            float z  = __shfl_sync(0xffffffffu, zv, t);
            float nr = fmaf(wre, sre, z);
            nr       = fmaf(-wim, sim, nr);
            float ni = fmaf(wim, sre, wre * sim);
            sre = nr;
            sim = ni;
            S[t][lane] = fmaf(ca, sre, cb * sim);
        }
        __syncwarp();
        ull a0 = 0ULL, a1 = 0ULL, a2 = 0ULL, a3 = 0ULL;
        const float* row = &S[lane][0];
#pragma unroll
        for (int q = 0; q < 8; q += 2) {
            ulonglong2 p0 = *(const ulonglong2*)(row + q * 4);
            ulonglong2 p1 = *(const ulonglong2*)(row + q * 4 + 4);
            add2(a0, p0.x);
            add2(a1, p0.y);
            add2(a2, p1.x);
            add2(a3, p1.y);
        }
        add2(a0, a2);
        add2(a1, a3);
        add2(a0, a1);
        float2 fr = unpack2(a0);
        float acc = fr.x + fr.y;

        float yv = fmaf(Dh, zv, acc);
        float u  = 0.7978845608028654f * fmaf(0.044715f, yv * yv * yv, yv);
        float gv = yv / (1.0f + __expf(-2.0f * u));
        __nv_bfloat16 bh = __float2bfloat16(gv);
        __nv_bfloat16 bl = __float2bfloat16(gv - __bfloat162float(bh));
        yh[l0 + lane] = bh;
        yl[l0 + lane] = bl;
        __syncwarp();
        zv = zn;
    }
}

// ===========================================================================
// FUSED v2: HMMA GEMM (bf16 3-term split, fp32 acc) + bias + GLU + residual +
// channel LayerNorm. NOW 2 CTAs/SM: CTA = 32 rows x 512 j, 256 threads /
// 8 warps (jo = wid owns 64 j, all 32 rows), k-chunks of 16, double-buffered.
// acc = 64 regs/thread; smem ~101KB/CTA -> 2 resident CTAs overlap stalls.
// A tile: 16 k-rows x 32 pos bf16 (64B data, 80B stride, trans ldsm).
// B tile: 512 j-rows x 16 k bf16 (32B data, 48B stride).
// ===========================================================================
#define F2A_STRIDE 80
#define F2A_TILE   (16 * F2A_STRIDE)               // 1280
#define F2B_STRIDE 48
#define F2B_TILE   (512 * F2B_STRIDE)              // 24576
#define F2_AH      0
#define F2_AL      F2A_TILE
#define F2_BH      (2 * F2A_TILE)
#define F2_BL      (2 * F2A_TILE + F2B_TILE)
#define F2_BUF     (2 * F2A_TILE + 2 * F2B_TILE)   // 51712
#define FUSED2_SMEM (2 * F2_BUF)                   // 103424
#define E2_G2      0                               // f32 [32][260] = 33280
#define E2_RES     (32 * 260 * 4)                  // f32 [32][260]

__global__ void __launch_bounds__(256, 2) fused_glu_ln_kernel(
    const float* __restrict__ out_b, const float* __restrict__ ln_w,
    const float* __restrict__ ln_b, int layer) {
    extern __shared__ char smem[];
    __shared__ float s_ob[512];
    __shared__ float s_lnw[HCH];
    __shared__ float s_lnb[HCH];
    __shared__ float s_mu[32];
    __shared__ float s_rs[32];

    int tid  = threadIdx.x;
    int wid  = tid >> 5;
    int lane = tid & 31;
    int row0 = blockIdx.x * 32;           // position rows, in [0, B*L)
    int b    = row0 >> 12;
    int pos0 = row0 & (LSEQ - 1);

    s_ob[tid]       = __ldg(&out_b[layer * 512 + tid]);
    s_ob[tid + 256] = __ldg(&out_b[layer * 512 + tid + 256]);
    if (tid < HCH) {
        s_lnw[tid] = __ldg(&ln_w[layer * HCH + tid]);
        s_lnb[tid] = __ldg(&ln_b[layer * HCH + tid]);
    }

    const __nv_bfloat16* Ah = g_yh + ((size_t)(b * HCH)) * LSEQ + pos0;
    const __nv_bfloat16* Al = g_yl + ((size_t)(b * HCH)) * LSEQ + pos0;
    const __nv_bfloat16* Bh = g_wh + (size_t)layer * 512 * HCH;
    const __nv_bfloat16* Bl = g_wl + (size_t)layer * 512 * HCH;

    uint32_t sb = smem_u32(smem);

    // staging maps (256 threads)
    int a_kr  = tid >> 2;        // only tid<64 used (k-row 0..15)
    int a_seg = tid & 3;         // 16B segment of 64B A row
    int b_jr0 = tid >> 1;        // 0..127 (then +128*i, 4 rows total... 2 iters)
    int b_seg = tid & 1;         // 16B segment of 32B B row

    float acc[16][4];
#pragma unroll
    for (int t = 0; t < 16; t++)
#pragma unroll
        for (int e = 0; e < 4; e++) acc[t][e] = 0.0f;

    int jo = wid;                // 0..7 (64-j octant); all warps cover 32 rows

    // stage chunk 0
    {
        uint32_t base = sb;
        if (tid < 64) {
            uint32_t d = base + a_kr * F2A_STRIDE + a_seg * 16;
            size_t go = (size_t)a_kr * LSEQ + a_seg * 8;
            cp16(d + F2_AH, Ah + go);
            cp16(d + F2_AL, Al + go);
        }
#pragma unroll
        for (int i = 0; i < 2; i++) {
            int jr = b_jr0 + i * 128;
            uint32_t d = base + jr * F2B_STRIDE + b_seg * 16;
            size_t go = (size_t)jr * HCH + b_seg * 8;
            cp16(d + F2_BH, Bh + go);
            cp16(d + F2_BL, Bl + go);
            jr += 256;
            d = base + jr * F2B_STRIDE + b_seg * 16;
            go = (size_t)jr * HCH + b_seg * 8;
            cp16(d + F2_BH, Bh + go);
            cp16(d + F2_BL, Bl + go);
        }
        CP_COMMIT();
    }

    // A fragment address pieces (trans ldmatrix, 16 k-rows)
    int f_kr = (lane & 7) + ((lane >> 4) << 3);   // source k row 0..15
    int f_mc = ((lane >> 3) & 1) * 8;             // m col 0 or 8

    int buf = 0;
    for (int ch = 0; ch < 16; ch++) {
        if (ch < 15) {
            uint32_t base = sb + (buf ^ 1) * F2_BUF;
            int k0 = (ch + 1) * 16;
            if (tid < 64) {
                uint32_t d = base + a_kr * F2A_STRIDE + a_seg * 16;
                size_t go = (size_t)(k0 + a_kr) * LSEQ + a_seg * 8;
                cp16(d + F2_AH, Ah + go);
                cp16(d + F2_AL, Al + go);
            }
#pragma unroll
            for (int i = 0; i < 2; i++) {
                int jr = b_jr0 + i * 128;
                uint32_t d = base + jr * F2B_STRIDE + b_seg * 16;
                size_t go = (size_t)jr * HCH + k0 + b_seg * 8;
                cp16(d + F2_BH, Bh + go);
                cp16(d + F2_BL, Bl + go);
                jr += 256;
                d = base + jr * F2B_STRIDE + b_seg * 16;
                go = (size_t)jr * HCH + k0 + b_seg * 8;
                cp16(d + F2_BH, Bh + go);
                cp16(d + F2_BL, Bl + go);
            }
            CP_COMMIT();
            CP_WAIT1();
        } else {
            CP_WAIT0();
        }
        __syncthreads();

        uint32_t cbase = sb + buf * F2_BUF;
#pragma unroll
        for (int pass = 0; pass < 3; pass++) {
            uint32_t aoff = cbase + (pass == 2 ? F2_AL : F2_AH);
            uint32_t boff = cbase + (pass == 1 ? F2_BL : F2_BH);
            uint32_t af0[4], af1[4];
            ldsm4t(af0, aoff + f_kr * F2A_STRIDE + f_mc * 2);
            ldsm4t(af1, aoff + f_kr * F2A_STRIDE + (16 + f_mc) * 2);
#pragma unroll
            for (int ng = 0; ng < 4; ng++) {
                uint32_t bfrag[4];
                uint32_t ba = boff +
                    (jo * 64 + ng * 16 + (lane & 15)) * F2B_STRIDE +
                    (lane >> 4) * 16;
                ldsm4(bfrag, ba);
                mma_bf16(acc[ng * 2],         af0, bfrag[0], bfrag[2]);
                mma_bf16(acc[ng * 2 + 1],     af0, bfrag[1], bfrag[3]);
                mma_bf16(acc[8 + ng * 2],     af1, bfrag[0], bfrag[2]);
                mma_bf16(acc[8 + ng * 2 + 1], af1, bfrag[1], bfrag[3]);
            }
        }
        __syncthreads();
        buf ^= 1;
    }

    // ---------------- fused epilogue (aliases tile smem) ----------------
    float* Gs2 = (float*)(smem + E2_G2);     // [32][260]
    float* Rsm = (float*)(smem + E2_RES);    // [32][260]

    // stage residual Rsm[pos][h] (256 threads, 8 iters of float4 over 32 pos)
    {
        const float* resb = g_h + (size_t)(b * HCH) * LSEQ + pos0;
#pragma unroll
        for (int i = 0; i < 8; i++) {
            int flat = tid + i * 256;        // 0..2047 float4 ids
            int h    = flat >> 3;
            int sg   = flat & 7;
            float4 v = *(const float4*)(resb + (size_t)h * LSEQ + sg * 4);
            Rsm[(sg * 4 + 0) * 260 + h] = v.x;
            Rsm[(sg * 4 + 1) * 260 + h] = v.y;
            Rsm[(sg * 4 + 2) * 260 + h] = v.z;
            Rsm[(sg * 4 + 3) * 260 + h] = v.w;
        }
    }
    // jo>=4 warps: write g2 + bias into Gs2 (j 256..511)
    if (jo >= 4) {
#pragma unroll
        for (int t = 0; t < 16; t++) {
            int mt = t >> 3;                 // 0..1 (16-row tile)
            int ng = (t >> 1) & 3;
            int j2 = (jo - 4) * 64 + ng * 16 + (t & 1) * 8 + (lane & 3) * 2;
            int r  = mt * 16 + (lane >> 2);
            float bb0 = s_ob[256 + j2];
            float bb1 = s_ob[256 + j2 + 1];
            Gs2[r * 260 + j2]           = acc[t][0] + bb0;
            Gs2[r * 260 + j2 + 1]       = acc[t][1] + bb1;
            Gs2[(r + 8) * 260 + j2]     = acc[t][2] + bb0;
            Gs2[(r + 8) * 260 + j2 + 1] = acc[t][3] + bb1;
        }
    }
    __syncthreads();

    // jo<4 warps: u = (g1+b1)*sigmoid(g2) + res, in place in Gs2 (h 0..255)
    if (jo < 4) {
#pragma unroll
        for (int t = 0; t < 16; t++) {
            int mt = t >> 3;
            int ng = (t >> 1) & 3;
            int h  = jo * 64 + ng * 16 + (t & 1) * 8 + (lane & 3) * 2;
            int r  = mt * 16 + (lane >> 2);
            float bb0 = s_ob[h];
            float bb1 = s_ob[h + 1];
#pragma unroll
            for (int e = 0; e < 4; e++) {
                int rr = r + ((e >> 1) << 3);
                int hh = h + (e & 1);
                float g1 = acc[t][e] + ((e & 1) ? bb1 : bb0);
                float g2 = Gs2[rr * 260 + hh];
                float u  = fmaf(g1, 1.0f / (1.0f + __expf(-g2)),
                                Rsm[rr * 260 + hh]);
                Gs2[rr * 260 + hh] = u;
            }
        }
    }
    __syncthreads();

    // per-row stats (8 threads per row, 256 threads / 32 rows)
    {
        int r = tid >> 3;
        int q = tid & 7;
        float s = 0.0f, sq = 0.0f;
#pragma unroll
        for (int i = 0; i < 32; i++) {
            float v = Gs2[r * 260 + q * 32 + i];
            s += v;
            sq = fmaf(v, v, sq);
        }
        s  += __shfl_xor_sync(0xffffffffu, s, 1);
        sq += __shfl_xor_sync(0xffffffffu, sq, 1);
        s  += __shfl_xor_sync(0xffffffffu, s, 2);
        sq += __shfl_xor_sync(0xffffffffu, sq, 2);
        s  += __shfl_xor_sync(0xffffffffu, s, 4);
        sq += __shfl_xor_sync(0xffffffffu, sq, 4);
        if (q == 0) {
            float m = s * (1.0f / 256.0f);
            s_mu[r] = m;
            s_rs[r] = rsqrtf(fmaf(-m, m, sq * (1.0f / 256.0f)) + 1e-5f);
        }
    }
    __syncthreads();

    // normalize + transposed write: thread h writes 32 positions
    {
        int h    = tid;
        float w  = s_lnw[h];
        float bb = s_lnb[h];
        float* outp = g_h + ((size_t)(b * HCH + h)) * LSEQ + pos0;
#pragma unroll
        for (int p4 = 0; p4 < 8; p4++) {
            int pp = p4 * 4;
            float4 o;
            float u0 = Gs2[(pp + 0) * 260 + h];
            float u1 = Gs2[(pp + 1) * 260 + h];
            float u2 = Gs2[(pp + 2) * 260 + h];
            float u3 = Gs2[(pp + 3) * 260 + h];
            o.x = fmaf((u0 - s_mu[pp + 0]) * s_rs[pp + 0], w, bb);
            o.y = fmaf((u1 - s_mu[pp + 1]) * s_rs[pp + 1], w, bb);
            o.z = fmaf((u2 - s_mu[pp + 2]) * s_rs[pp + 2], w, bb);
            o.w = fmaf((u3 - s_mu[pp + 3]) * s_rs[pp + 3], w, bb);
            *(float4*)(outp + p4 * 4) = o;
        }
    }
}

// ===========================================================================
// Decoder
// ===========================================================================
__global__ void __launch_bounds__(256) decoder_kernel(
    const float* __restrict__ dec_w, const float* __restrict__ dec_b,
    float* __restrict__ out) {
    __shared__ float wsh[DOUT * HCH];
    __shared__ float bsh[DOUT];
    int b    = blockIdx.y;
    int pos0 = blockIdx.x * 256;
    int tid  = threadIdx.x;
    for (int e = tid; e < DOUT * HCH; e += 256) wsh[e] = dec_w[e];
    if (tid < DOUT) bsh[tid] = dec_b[tid];
    __syncthreads();

    float acc[DOUT];
#pragma unroll
    for (int o = 0; o < DOUT; o++) acc[o] = bsh[o];

    const float* hp = g_h + (size_t)b * HCH * LSEQ + pos0 + tid;
    for (int h = 0; h < HCH; h++) {
        float xv = hp[(size_t)h * LSEQ];
#pragma unroll
        for (int o = 0; o < DOUT; o++)
            acc[o] = fmaf(xv, wsh[o * HCH + h], acc[o]);
    }
    float* op = out + ((size_t)(b * LSEQ) + pos0 + tid) * DOUT;
#pragma unroll
    for (int o = 0; o < DOUT; o++) op[o] = acc[o];
}

// ===========================================================================
extern "C" void kernel_launch(void* const* d_in, const int* in_sizes, int n_in,
                              void* d_out, int out_size) {
    const float* x          = (const float*)d_in[0];
    const float* enc_w      = (const float*)d_in[1];
    const float* enc_b      = (const float*)d_in[2];
    const float* log_dt     = (const float*)d_in[3];
    const float* log_A_real = (const float*)d_in[4];
    const float* A_imag     = (const float*)d_in[5];
    const float* C_re       = (const float*)d_in[6];
    const float* C_im       = (const float*)d_in[7];
    const float* Dv         = (const float*)d_in[8];
    const float* out_w      = (const float*)d_in[9];
    const float* out_b      = (const float*)d_in[10];
    const float* ln_w       = (const float*)d_in[11];
    const float* ln_b       = (const float*)d_in[12];
    const float* dec_w      = (const float*)d_in[13];
    const float* dec_b      = (const float*)d_in[14];
    float* out = (float*)d_out;

    size_t enc_smem = (size_t)(64 * HCH + 64 * 68) * sizeof(float);
    cudaFuncSetAttribute(encoder_kernel,
                         cudaFuncAttributeMaxDynamicSharedMemorySize,
                         (int)enc_smem);
    cudaFuncSetAttribute(fused_glu_ln_kernel,
                         cudaFuncAttributeMaxDynamicSharedMemorySize,
                         FUSED2_SMEM);

    prep_kernel<<<(NLAY * 512 * HCH + 255) / 256, 256>>>(
        log_dt, log_A_real, A_imag, C_re, C_im, out_w);
    encoder_kernel<<<dim3(LSEQ / 64, NBATCH), 256, enc_smem>>>(x, enc_w, enc_b);
    for (int layer = 0; layer < NLAY; layer++) {
        scan_kernel<<<1024, 128>>>(Dv, layer);
        fused_glu_ln_kernel<<<NBATCH * LSEQ / 32, 256, FUSED2_SMEM>>>(
            out_b, ln_w, ln_b, layer);
    }
    decoder_kernel<<<dim3(LSEQ / 256, NBATCH), 256>>>(dec_w, dec_b, out);
}